// round 12
// baseline (speedup 1.0000x reference)
#include <cuda_runtime.h>
#include <cuda_bf16.h>
#include <cstdint>
#include <cstddef>

#define NEDGES  1600000
#define NNODES  100000
#define OUTD    64
#define MTILE   128
#define THREADS 512
#define TPB     4
#define EDGE_BLOCKS (NEDGES / (MTILE * TPB))          // 3125
#define NODE_BLOCKS ((NNODES + MTILE - 1) / MTILE)    // 782
#define SCAN_BLOCKS ((NNODES + 1023) / 1024)          // 98

// ---- edge kernel smem layout (fp16, double-buffered A; C reuses dead A buf) ----
#define E_BIAS 0         // 64 floats
#define E_DST  256       // 512 ints
#define E_SRC  2304
#define E_BB   4352
#define E_EID  6400
#define E_A0   8448      // 32KB
#define E_A1   (E_A0 + 32768)
#define E_B    (E_A1 + 32768)   // 16KB
#define E_SZ   (E_B + 16384)    // 90368

// ---- node kernel smem layout ----
#define N_BIAS 0
#define N_BB   256
#define N_A    2048
#define N_B    (N_A + 32768)
#define N_SZ   (N_B + 16384)

// ---- device scratch ----
__device__ float g_agg[(size_t)NNODES * OUTD];
__device__ int   g_src[NEDGES];
__device__ int   g_dst[NEDGES];
__device__ int   g_batch[NNODES];
__device__ int   g_cnt[NNODES];
__device__ int   g_pos[NNODES];
__device__ int   g_bsum[SCAN_BLOCKS];
__device__ int   g_bpre[SCAN_BLOCKS];
__device__ int   g_ssrc[NEDGES];
__device__ int   g_sdst[NEDGES];
__device__ int   g_sbb[NEDGES];
__device__ int   g_seid[NEDGES];
__device__ __align__(16) unsigned char g_w1f16[16384];
__device__ __align__(16) unsigned char g_w2f16[16384];

// ================= helpers =================
__device__ __forceinline__ uint32_t smem_u32(const void* p) {
    uint32_t a;
    asm("{ .reg .u64 t; cvta.to.shared.u64 t, %1; cvt.u32.u64 %0, t; }" : "=r"(a) : "l"(p));
    return a;
}
__device__ __forceinline__ uint32_t pack_f16(float a, float b) {
    uint32_t w;
    asm("cvt.rn.f16x2.f32 %0, %1, %2;" : "=r"(w) : "f"(b), "f"(a));
    return w;
}
__device__ __forceinline__ uint32_t swz(int r, uint32_t w) {
    return (uint32_t)r * 256u + ((w ^ (uint32_t)((r & 7) << 2)) << 2);
}
__device__ __forceinline__ void ldsm4(uint32_t addr, uint32_t* r) {
    asm volatile("ldmatrix.sync.aligned.m8n8.x4.shared.b16 {%0,%1,%2,%3}, [%4];"
                 : "=r"(r[0]), "=r"(r[1]), "=r"(r[2]), "=r"(r[3]) : "r"(addr));
}
__device__ __forceinline__ void mma_f16(float* d, const uint32_t* a, uint32_t b0, uint32_t b1) {
    asm volatile(
        "mma.sync.aligned.m16n8k16.row.col.f32.f16.f16.f32 "
        "{%0,%1,%2,%3},{%4,%5,%6,%7},{%8,%9},{%0,%1,%2,%3};"
        : "+f"(d[0]), "+f"(d[1]), "+f"(d[2]), "+f"(d[3])
        : "r"(a[0]), "r"(a[1]), "r"(a[2]), "r"(a[3]), "r"(b0), "r"(b1));
}
__device__ __forceinline__ void red4(float* p, float v0, float v1, float v2, float v3) {
    asm volatile("red.global.add.v4.f32 [%0], {%1,%2,%3,%4};"
                 :: "l"(p), "f"(v0), "f"(v1), "f"(v2), "f"(v3) : "memory");
}
__device__ __host__ __forceinline__ int perm_col(int n) {
    int p = n & 15;
    return (n & ~15) + ((p & 7) >> 1) * 4 + ((p >> 3) << 1) + (p & 1);
}
// fp32 epilogue tile: swizzled float4 groups, 64 floats/row
__device__ __forceinline__ uint32_t c_off(int r, int g) {
    return (uint32_t)r * 64u + (uint32_t)((g ^ (r & 7)) << 2);
}

// ==================== prep chain ====================
__device__ __forceinline__ bool detect_is64(const long long* e64) {
    bool ok = true;
    #pragma unroll
    for (int i = 0; i < 8; i++)
        ok &= ((unsigned long long)e64[i] < (unsigned long long)NNODES);
    return ok;
}

__global__ void prep_kernel(const void* ei_raw, const void* batch_raw,
                            const float* __restrict__ W1, const float* __restrict__ W2) {
    const bool is64 = detect_is64((const long long*)ei_raw);
    const long long* e64 = (const long long*)ei_raw;
    const int*       e32 = (const int*)ei_raw;
    const long long* b64 = (const long long*)batch_raw;
    const int*       b32 = (const int*)batch_raw;

    const int i0 = blockIdx.x * blockDim.x + threadIdx.x;
    const int stride = gridDim.x * blockDim.x;

    for (int e = i0; e < NEDGES; e += stride) {
        g_src[e] = is64 ? (int)e64[e]          : e32[e];
        g_dst[e] = is64 ? (int)e64[NEDGES + e] : e32[NEDGES + e];
    }
    for (int n = i0; n < NNODES; n += stride) {
        g_batch[n] = is64 ? (int)b64[n] : b32[n];
        g_cnt[n] = 0;
    }

    float4* p = (float4*)g_agg;
    const int nz = NNODES * OUTD / 4;
    float4 z = make_float4(0.f, 0.f, 0.f, 0.f);
    for (int i = i0; i < nz; i += stride) p[i] = z;

    for (int q = i0; q < 4096; q += stride) {
        int n = q >> 6, k = (q & 63) << 1;
        int l = perm_col(n);
        uint32_t off = swz(n, (uint32_t)(k >> 1));
        *(uint32_t*)(g_w1f16 + off) =
            pack_f16(W1[(size_t)k * OUTD + l], W1[(size_t)(k + 1) * OUTD + l]);
        *(uint32_t*)(g_w2f16 + off) =
            pack_f16(W2[(size_t)k * OUTD + l], W2[(size_t)(k + 1) * OUTD + l]);
    }
}

__global__ void hist_kernel() {
    int e = blockIdx.x * blockDim.x + threadIdx.x;
    if (e < NEDGES) atomicAdd(&g_cnt[g_dst[e]], 1);
}

__global__ void scan_block_kernel() {   // 98 blocks x 1024
    __shared__ int s[1024];
    int tid = threadIdx.x;
    int i = blockIdx.x * 1024 + tid;
    int v = (i < NNODES) ? g_cnt[i] : 0;
    s[tid] = v;
    __syncthreads();
    #pragma unroll
    for (int off = 1; off < 1024; off <<= 1) {
        int t = (tid >= off) ? s[tid - off] : 0;
        __syncthreads();
        s[tid] += t;
        __syncthreads();
    }
    if (i < NNODES) g_pos[i] = s[tid] - v;     // exclusive within block
    if (tid == 1023) g_bsum[blockIdx.x] = s[1023];
}

__global__ void scan_tot_kernel() {
    if (threadIdx.x == 0) {
        int acc = 0;
        for (int b = 0; b < SCAN_BLOCKS; b++) { g_bpre[b] = acc; acc += g_bsum[b]; }
    }
}

__global__ void add_base_kernel() {   // 98 blocks x 1024
    int i = blockIdx.x * 1024 + threadIdx.x;
    if (i < NNODES) g_pos[i] += g_bpre[blockIdx.x];
}

__global__ void sort_kernel() {   // 3125 x 512
    int e = blockIdx.x * blockDim.x + threadIdx.x;
    if (e < NEDGES) {
        int d = g_dst[e];
        int s = g_src[e];
        int pos = atomicAdd(&g_pos[d], 1);
        g_ssrc[pos] = s;
        g_sdst[pos] = d;
        g_sbb[pos]  = g_batch[s];
        g_seid[pos] = e;
    }
}

// ==================== GEMM pieces ====================
__device__ __forceinline__ void init_acc(const float* bias, int nh, int lane, float acc[4][4]) {
    #pragma unroll
    for (int jl = 0; jl < 4; jl++) {
        int np = nh * 2 + (jl >> 1);
        int c = np * 16 + (lane & 3) * 4 + (jl & 1) * 2;
        float b0 = bias[c], b1 = bias[c + 1];
        acc[jl][0] = b0; acc[jl][1] = b1; acc[jl][2] = b0; acc[jl][3] = b1;
    }
}

__device__ __forceinline__ void gemm_half(uint32_t sb, uint32_t aOff, uint32_t bOff,
                                          int mt, int nh, int lane,
                                          float acc[4][4], int ks0) {
    const int j  = lane >> 3;
    const int rr = lane & 7;
    const uint32_t xo = (uint32_t)(rr << 2);
    const int rowA = mt * 16 + ((j & 1) << 3) + rr;
    const int rowB = ((j & 1) << 3) + rr;
    const uint32_t ksg = (uint32_t)((j >> 1) << 2);

    #pragma unroll
    for (int kk = 0; kk < 4; kk++) {
        const int ks = ks0 + kk;
        const uint32_t byte = (((uint32_t)(ks * 8) + ksg) ^ xo) << 2;
        uint32_t a[4];
        ldsm4(sb + aOff + (uint32_t)rowA * 256 + byte, a);
        #pragma unroll
        for (int p = 0; p < 2; p++) {
            const int np = nh * 2 + p;
            uint32_t b[4];
            ldsm4(sb + bOff + (uint32_t)(rowB + np * 16) * 256 + byte, b);
            mma_f16(acc[2*p],   a, b[0], b[2]);
            mma_f16(acc[2*p+1], a, b[1], b[3]);
        }
    }
}

// ==================== edge kernel ====================
__device__ __forceinline__ void gather_half(
    const float4* x4, const float4* ea4, const float4* u4,
    const int* sDst, const int* sSrc, const int* sBB, const int* sEid,
    int t, int it0, int tid, float4* gv)
{
    #pragma unroll
    for (int i = 0; i < 4; i++) {
        int idx = tid + (it0 + i) * THREADS;
        int r = idx >> 5, seg = idx & 31;
        int row = t * MTILE + r;
        int q = seg >> 3, f = seg & 7;
        const float4* p;
        if (q == 0)      p = x4  + (size_t)sDst[row] * 8 + f;
        else if (q == 1) p = x4  + (size_t)sSrc[row] * 8 + f;
        else if (q == 2) p = ea4 + (size_t)sEid[row] * 8 + f;
        else             p = u4  + (size_t)sBB[row] * 8 + f;
        gv[i] = *p;
    }
}
__device__ __forceinline__ void stash_half(char* smem, uint32_t aOff,
                                           int it0, int tid, const float4* gv)
{
    #pragma unroll
    for (int i = 0; i < 4; i++) {
        int idx = tid + (it0 + i) * THREADS;
        int r = idx >> 5, seg = idx & 31;
        uint32_t w0 = (uint32_t)(seg * 2);
        *(uint32_t*)(smem + aOff + swz(r, w0))     = pack_f16(gv[i].x, gv[i].y);
        *(uint32_t*)(smem + aOff + swz(r, w0 + 1)) = pack_f16(gv[i].z, gv[i].w);
    }
}

__global__ void __launch_bounds__(THREADS, 2) edge_kernel(
    const float* __restrict__ x, const float* __restrict__ ea,
    const float* __restrict__ u, const float* __restrict__ b1)
{
    extern __shared__ char smem[];
    const uint32_t sb = smem_u32(smem);
    const int tid = threadIdx.x;
    const int lane = tid & 31, warp = tid >> 5;
    const int mt = warp >> 1, nh = warp & 1;

    int* sDst = (int*)(smem + E_DST);
    int* sSrc = (int*)(smem + E_SRC);
    int* sBB  = (int*)(smem + E_BB);
    int* sEid = (int*)(smem + E_EID);

    const int eBase = blockIdx.x * (MTILE * TPB);
    {   // sorted indices for this block's 512 edges
        int e = eBase + tid;
        sSrc[tid] = g_ssrc[e];
        sDst[tid] = g_sdst[e];
        sBB[tid]  = g_sbb[e];
        sEid[tid] = g_seid[e];
    }
    if (tid < OUTD) ((float*)(smem + E_BIAS))[tid] = b1[tid];
    {   // W1 fp16 (16KB) once per block
        const float4* w4 = (const float4*)g_w1f16;
        float4* d4 = (float4*)(smem + E_B);
        #pragma unroll
        for (int i = 0; i < 1024 / THREADS; i++)
            d4[tid + i * THREADS] = w4[tid + i * THREADS];
    }
    __syncthreads();

    const float4* x4  = (const float4*)x;
    const float4* ea4 = (const float4*)ea;
    const float4* u4  = (const float4*)u;

    // prologue: fill A0 for tile 0
    {
        float4 gv[4];
        gather_half(x4, ea4, u4, sDst, sSrc, sBB, sEid, 0, 0, tid, gv);
        stash_half(smem, E_A0, 0, tid, gv);
        gather_half(x4, ea4, u4, sDst, sSrc, sBB, sEid, 0, 4, tid, gv);
        stash_half(smem, E_A0, 4, tid, gv);
    }
    __syncthreads();

    const int ra = mt * 16 + (lane >> 2);
    const int rb = ra + 8;

    for (int t = 0; t < TPB; t++) {
        const uint32_t aCur = (t & 1) ? E_A1 : E_A0;
        const uint32_t aNxt = (t & 1) ? E_A0 : E_A1;

        float acc[4][4];
        init_acc((const float*)(smem + E_BIAS), nh, lane, acc);

        float4 gv[4];
        if (t + 1 < TPB)
            gather_half(x4, ea4, u4, sDst, sSrc, sBB, sEid, t + 1, 0, tid, gv);

        gemm_half(sb, aCur, E_B, mt, nh, lane, acc, 0);

        if (t + 1 < TPB) {
            stash_half(smem, aNxt, 0, tid, gv);
            gather_half(x4, ea4, u4, sDst, sSrc, sBB, sEid, t + 1, 4, tid, gv);
        }

        gemm_half(sb, aCur, E_B, mt, nh, lane, acc, 4);

        if (t + 1 < TPB)
            stash_half(smem, aNxt, 4, tid, gv);

        __syncthreads();   // (1) aCur reads done everywhere; aNxt stash visible

        {   // write relu'd fp32 results into dead aCur buffer (swizzled)
            float* C = (float*)(smem + aCur);
            #pragma unroll
            for (int jl = 0; jl < 4; jl++) {
                int np = nh * 2 + (jl >> 1);
                int c = np * 16 + (lane & 3) * 4 + (jl & 1) * 2;
                int g = c >> 2;
                *(float2*)&C[c_off(ra, g) + (c & 3)] =
                    make_float2(fmaxf(acc[jl][0], 0.f), fmaxf(acc[jl][1], 0.f));
                *(float2*)&C[c_off(rb, g) + (c & 3)] =
                    make_float2(fmaxf(acc[jl][2], 0.f), fmaxf(acc[jl][3], 0.f));
            }
        }
        __syncthreads();   // (2) C visible

        if (tid < 128) {   // segmented run-reduction over sorted dst, 16 rows/thread
            const float* C = (const float*)(smem + aCur);
            const int chunk = tid >> 4, cg = tid & 15;
            const int r0 = chunk * 16;
            const int* dstRow = sDst + t * MTILE;
            float4 s = *(const float4*)&C[c_off(r0, cg)];
            int d = dstRow[r0];
            #pragma unroll
            for (int r = r0 + 1; r < r0 + 16; r++) {
                float4 v = *(const float4*)&C[c_off(r, cg)];
                int dn = dstRow[r];
                if (dn != d) {
                    red4(g_agg + (size_t)d * OUTD + cg * 4, s.x, s.y, s.z, s.w);
                    s = v; d = dn;
                } else {
                    s.x += v.x; s.y += v.y; s.z += v.z; s.w += v.w;
                }
            }
            red4(g_agg + (size_t)d * OUTD + cg * 4, s.x, s.y, s.z, s.w);
        }
        __syncthreads();   // (3) C reads done before next tile stashes into this buf
    }
}

// ==================== node kernel (fp16 1-pass) ====================
__global__ void __launch_bounds__(THREADS, 2) node_kernel(
    const float* __restrict__ x, const float* __restrict__ u,
    const float* __restrict__ b2, float* __restrict__ out)
{
    extern __shared__ char smem[];
    const uint32_t sb = smem_u32(smem);
    const int tid = threadIdx.x;
    const long long n0 = (long long)blockIdx.x * MTILE;

    int* sBB = (int*)(smem + N_BB);
    if (tid < MTILE) {
        long long nn = n0 + tid;
        if (nn >= NNODES) nn = NNODES - 1;
        sBB[tid] = g_batch[nn];
    }
    if (tid < OUTD) ((float*)(smem + N_BIAS))[tid] = b2[tid];
    {
        const float4* w4 = (const float4*)g_w2f16;
        float4* d4 = (float4*)(smem + N_B);
        #pragma unroll
        for (int i = 0; i < 1024 / THREADS; i++)
            d4[tid + i * THREADS] = w4[tid + i * THREADS];
    }
    __syncthreads();

    {   // full 128x32 float4 coverage = 8 iters/thread
        const float4* x4 = (const float4*)x;
        const float4* u4 = (const float4*)u;
        const float4* agg4 = (const float4*)g_agg;
        float4 gv[8];
        int gr[8], gseg[8];
        #pragma unroll
        for (int it = 0; it < 8; it++) {
            int idx = tid + it * THREADS;
            int r = idx >> 5, seg = idx & 31;
            gr[it] = r; gseg[it] = seg;
            long long nn = n0 + r;
            if (nn >= NNODES) nn = NNODES - 1;
            const float4* p;
            if (seg < 8)       p = x4   + (size_t)nn * 8 + seg;
            else if (seg < 24) p = agg4 + (size_t)nn * 16 + (seg - 8);
            else               p = u4   + (size_t)sBB[r] * 8 + (seg - 24);
            gv[it] = *p;
        }
        #pragma unroll
        for (int it = 0; it < 8; it++) {
            uint32_t w0 = (uint32_t)(gseg[it] * 2);
            *(uint32_t*)(smem + N_A + swz(gr[it], w0))     = pack_f16(gv[it].x, gv[it].y);
            *(uint32_t*)(smem + N_A + swz(gr[it], w0 + 1)) = pack_f16(gv[it].z, gv[it].w);
        }
    }
    __syncthreads();

    const int lane = tid & 31, warp = tid >> 5;
    const int mt = warp >> 1, nh = warp & 1;
    float acc[4][4];
    init_acc((const float*)(smem + N_BIAS), nh, lane, acc);

    gemm_half(sb, N_A, N_B, mt, nh, lane, acc, 0);
    gemm_half(sb, N_A, N_B, mt, nh, lane, acc, 4);

    {
        long long ra = n0 + mt * 16 + (lane >> 2);
        long long rb = ra + 8;
        #pragma unroll
        for (int p = 0; p < 2; p++) {
            const int np = nh * 2 + p;
            int c = np * 16 + (lane & 3) * 4;
            if (ra < NNODES)
                *(float4*)(out + (size_t)ra * OUTD + c) = make_float4(
                    fmaxf(acc[2*p][0], 0.f),   fmaxf(acc[2*p][1], 0.f),
                    fmaxf(acc[2*p+1][0], 0.f), fmaxf(acc[2*p+1][1], 0.f));
            if (rb < NNODES)
                *(float4*)(out + (size_t)rb * OUTD + c) = make_float4(
                    fmaxf(acc[2*p][2], 0.f),   fmaxf(acc[2*p][3], 0.f),
                    fmaxf(acc[2*p+1][2], 0.f), fmaxf(acc[2*p+1][3], 0.f));
        }
    }
}

// ==================== launcher ====================
extern "C" void kernel_launch(void* const* d_in, const int* in_sizes, int n_in,
                              void* d_out, int out_size) {
    const float* x     = (const float*)d_in[0];
    const void*  ei    = d_in[1];
    const float* ea    = (const float*)d_in[2];
    const float* u     = (const float*)d_in[3];
    const void*  batch = d_in[4];
    const float* W1    = (const float*)d_in[5];
    const float* b1    = (const float*)d_in[6];
    const float* W2    = (const float*)d_in[7];
    const float* b2    = (const float*)d_in[8];
    float* out = (float*)d_out;

    cudaFuncSetAttribute(edge_kernel, cudaFuncAttributeMaxDynamicSharedMemorySize, E_SZ);
    cudaFuncSetAttribute(node_kernel, cudaFuncAttributeMaxDynamicSharedMemorySize, N_SZ);

    prep_kernel<<<1480, 256>>>(ei, batch, W1, W2);
    hist_kernel<<<EDGE_BLOCKS, 512>>>();
    scan_block_kernel<<<SCAN_BLOCKS, 1024>>>();
    scan_tot_kernel<<<1, 32>>>();
    add_base_kernel<<<SCAN_BLOCKS, 1024>>>();
    sort_kernel<<<EDGE_BLOCKS, 512>>>();
    edge_kernel<<<EDGE_BLOCKS, THREADS, E_SZ>>>(x, ea, u, b1);
    node_kernel<<<NODE_BLOCKS, THREADS, N_SZ>>>(x, u, b2, out);
}

// round 13
// speedup vs baseline: 1.3355x; 1.3355x over previous
#include <cuda_runtime.h>
#include <cuda_bf16.h>
#include <cstdint>
#include <cstddef>

#define NEDGES  1600000
#define NNODES  100000
#define OUTD    64
#define MTILE   128
#define THREADS 512
#define TPB     4
#define GROUPS  (NEDGES / (MTILE * TPB))              // 3125
#define EDGE_GRID 296                                  // 148 SMs x 2 CTAs, persistent
#define NODE_BLOCKS ((NNODES + MTILE - 1) / MTILE)    // 782

// ---- edge kernel smem layout (fp16, double-buffered A) ----
#define E_BIAS 0         // 64 floats
#define E_DST  256       // 512 ints
#define E_SRC  2304
#define E_BB   4352
#define E_A0   7168      // 128x128 fp16 (32KB), swizzled 256B rows
#define E_A1   (E_A0 + 32768)
#define E_B    (E_A1 + 32768)   // 64x128 fp16 (16KB)
#define E_SZ   (E_B + 16384)    // 89088

// ---- node kernel smem layout (fp16 single buffer) ----
#define N_BIAS 0
#define N_BB   256       // 128 ints
#define N_A    2048      // 32KB
#define N_B    (N_A + 32768)
#define N_SZ   (N_B + 16384)    // 51200

// ---- device scratch ----
__device__ float g_agg[(size_t)NNODES * OUTD];
__device__ int   g_src[NEDGES];
__device__ int   g_dst[NEDGES];
__device__ int   g_batch[NNODES];
__device__ __align__(16) unsigned char g_w1f16[16384];   // W1 fp16, B^T swizzled
__device__ __align__(16) unsigned char g_w2f16[16384];   // W2 fp16, B^T swizzled

// ================= helpers =================
__device__ __forceinline__ uint32_t smem_u32(const void* p) {
    uint32_t a;
    asm("{ .reg .u64 t; cvta.to.shared.u64 t, %1; cvt.u32.u64 %0, t; }" : "=r"(a) : "l"(p));
    return a;
}
__device__ __forceinline__ uint32_t pack_f16(float a, float b) {
    uint32_t w;
    asm("cvt.rn.f16x2.f32 %0, %1, %2;" : "=r"(w) : "f"(b), "f"(a));
    return w;
}
// swizzled byte offset inside a [row][64-word] tile: word ^= (row&7)<<2
__device__ __forceinline__ uint32_t swz(int r, uint32_t w) {
    return (uint32_t)r * 256u + ((w ^ (uint32_t)((r & 7) << 2)) << 2);
}
__device__ __forceinline__ void ldsm4(uint32_t addr, uint32_t* r) {
    asm volatile("ldmatrix.sync.aligned.m8n8.x4.shared.b16 {%0,%1,%2,%3}, [%4];"
                 : "=r"(r[0]), "=r"(r[1]), "=r"(r[2]), "=r"(r[3]) : "r"(addr));
}
__device__ __forceinline__ void mma_f16(float* d, const uint32_t* a, uint32_t b0, uint32_t b1) {
    asm volatile(
        "mma.sync.aligned.m16n8k16.row.col.f32.f16.f16.f32 "
        "{%0,%1,%2,%3},{%4,%5,%6,%7},{%8,%9},{%0,%1,%2,%3};"
        : "+f"(d[0]), "+f"(d[1]), "+f"(d[2]), "+f"(d[3])
        : "r"(a[0]), "r"(a[1]), "r"(a[2]), "r"(a[3]), "r"(b0), "r"(b1));
}
__device__ __forceinline__ void red4(float* p, float v0, float v1, float v2, float v3) {
    asm volatile("red.global.add.v4.f32 [%0], {%1,%2,%3,%4};"
                 :: "l"(p), "f"(v0), "f"(v1), "f"(v2), "f"(v3) : "memory");
}
// column permutation: physical B^T row n holds weights of logical output column perm_col(n).
__device__ __host__ __forceinline__ int perm_col(int n) {
    int p = n & 15;
    return (n & ~15) + ((p & 7) >> 1) * 4 + ((p >> 3) << 1) + (p & 1);
}

// ==================== prep ====================
__device__ __forceinline__ bool detect_is64(const long long* e64) {
    bool ok = true;
    #pragma unroll
    for (int i = 0; i < 8; i++)
        ok &= ((unsigned long long)e64[i] < (unsigned long long)NNODES);
    return ok;
}

__global__ void prep_kernel(const void* ei_raw, const void* batch_raw,
                            const float* __restrict__ W1, const float* __restrict__ W2) {
    const bool is64 = detect_is64((const long long*)ei_raw);
    const long long* e64 = (const long long*)ei_raw;
    const int*       e32 = (const int*)ei_raw;
    const long long* b64 = (const long long*)batch_raw;
    const int*       b32 = (const int*)batch_raw;

    const int i0 = blockIdx.x * blockDim.x + threadIdx.x;
    const int stride = gridDim.x * blockDim.x;

    for (int e = i0; e < NEDGES; e += stride) {
        g_src[e] = is64 ? (int)e64[e]          : e32[e];
        g_dst[e] = is64 ? (int)e64[NEDGES + e] : e32[NEDGES + e];
    }
    for (int n = i0; n < NNODES; n += stride)
        g_batch[n] = is64 ? (int)b64[n] : b32[n];

    float4* p = (float4*)g_agg;
    const int nz = NNODES * OUTD / 4;
    float4 z = make_float4(0.f, 0.f, 0.f, 0.f);
    for (int i = i0; i < nz; i += stride) p[i] = z;

    for (int q = i0; q < 4096; q += stride) {   // 64 n x 64 k-pairs
        int n = q >> 6, k = (q & 63) << 1;
        int l = perm_col(n);
        uint32_t off = swz(n, (uint32_t)(k >> 1));
        *(uint32_t*)(g_w1f16 + off) =
            pack_f16(W1[(size_t)k * OUTD + l], W1[(size_t)(k + 1) * OUTD + l]);
        *(uint32_t*)(g_w2f16 + off) =
            pack_f16(W2[(size_t)k * OUTD + l], W2[(size_t)(k + 1) * OUTD + l]);
    }
}

// ==================== shared pieces ====================
__device__ __forceinline__ void init_acc(const float* bias, int nh, int lane, float acc[4][4]) {
    #pragma unroll
    for (int jl = 0; jl < 4; jl++) {
        int np = nh * 2 + (jl >> 1);
        int c = np * 16 + (lane & 3) * 4 + (jl & 1) * 2;
        float b0 = bias[c], b1 = bias[c + 1];
        acc[jl][0] = b0; acc[jl][1] = b1; acc[jl][2] = b0; acc[jl][3] = b1;
    }
}

// half of the fp16 GEMM: ks in [ks0, ks0+4)
__device__ __forceinline__ void gemm_half(uint32_t sb, uint32_t aOff, uint32_t bOff,
                                          int mt, int nh, int lane,
                                          float acc[4][4], int ks0) {
    const int j  = lane >> 3;
    const int rr = lane & 7;
    const uint32_t xo = (uint32_t)(rr << 2);
    const int rowA = mt * 16 + ((j & 1) << 3) + rr;
    const int rowB = ((j & 1) << 3) + rr;
    const uint32_t ksg = (uint32_t)((j >> 1) << 2);

    #pragma unroll
    for (int kk = 0; kk < 4; kk++) {
        const int ks = ks0 + kk;
        const uint32_t byte = (((uint32_t)(ks * 8) + ksg) ^ xo) << 2;
        uint32_t a[4];
        ldsm4(sb + aOff + (uint32_t)rowA * 256 + byte, a);
        #pragma unroll
        for (int p = 0; p < 2; p++) {
            const int np = nh * 2 + p;
            uint32_t b[4];
            ldsm4(sb + bOff + (uint32_t)(rowB + np * 16) * 256 + byte, b);
            mma_f16(acc[2*p],   a, b[0], b[2]);
            mma_f16(acc[2*p+1], a, b[1], b[3]);
        }
    }
}

// ==================== edge kernel (persistent, fp16, pipelined) ====================
__device__ __forceinline__ void gather_half(
    const float4* x4, const float4* ea4, const float4* u4,
    const int* sDst, const int* sSrc, const int* sBB,
    long long eBase, int t, int it0, int tid, float4* gv)
{
    #pragma unroll
    for (int i = 0; i < 4; i++) {
        int idx = tid + (it0 + i) * THREADS;
        int r = idx >> 5, seg = idx & 31;
        int row = t * MTILE + r;
        int q = seg >> 3, f = seg & 7;
        const float4* p;
        if (q == 0)      p = x4  + (size_t)sDst[row] * 8 + f;
        else if (q == 1) p = x4  + (size_t)sSrc[row] * 8 + f;
        else if (q == 2) p = ea4 + (size_t)(eBase + row) * 8 + f;
        else             p = u4  + (size_t)sBB[row] * 8 + f;
        gv[i] = *p;
    }
}
__device__ __forceinline__ void stash_half(char* smem, uint32_t aOff,
                                           int it0, int tid, const float4* gv)
{
    #pragma unroll
    for (int i = 0; i < 4; i++) {
        int idx = tid + (it0 + i) * THREADS;
        int r = idx >> 5, seg = idx & 31;
        uint32_t w0 = (uint32_t)(seg * 2);
        *(uint32_t*)(smem + aOff + swz(r, w0))     = pack_f16(gv[i].x, gv[i].y);
        *(uint32_t*)(smem + aOff + swz(r, w0 + 1)) = pack_f16(gv[i].z, gv[i].w);
    }
}

__global__ void __launch_bounds__(THREADS, 2) edge_kernel(
    const float* __restrict__ x, const float* __restrict__ ea,
    const float* __restrict__ u, const float* __restrict__ b1)
{
    extern __shared__ char smem[];
    const uint32_t sb = smem_u32(smem);
    const int tid = threadIdx.x;
    const int lane = tid & 31, warp = tid >> 5;
    const int mt = warp >> 1, nh = warp & 1;

    int* sDst = (int*)(smem + E_DST);
    int* sSrc = (int*)(smem + E_SRC);
    int* sBB  = (int*)(smem + E_BB);

    if (tid < OUTD) ((float*)(smem + E_BIAS))[tid] = b1[tid];
    {   // W1 fp16 (16KB) ONCE per persistent CTA
        const float4* w4 = (const float4*)g_w1f16;
        float4* d4 = (float4*)(smem + E_B);
        #pragma unroll
        for (int i = 0; i < 1024 / THREADS; i++)
            d4[tid + i * THREADS] = w4[tid + i * THREADS];
    }

    const float4* x4  = (const float4*)x;
    const float4* ea4 = (const float4*)ea;
    const float4* u4  = (const float4*)u;

    const int ra = mt * 16 + (lane >> 2);
    const int rb = ra + 8;

    for (int grp = blockIdx.x; grp < GROUPS; grp += gridDim.x) {
        const long long eBase = (long long)grp * (MTILE * TPB);

        {   // this group's 512 edge indices, one per thread
            int e = (int)eBase + tid;
            int s = g_src[e];
            sSrc[tid] = s;
            sDst[tid] = g_dst[e];
            sBB[tid]  = g_batch[s];
        }
        __syncthreads();   // indices visible (also W1/bias on first group)

        // prologue: fill A0 for tile 0 of this group
        {
            float4 gv[4];
            gather_half(x4, ea4, u4, sDst, sSrc, sBB, eBase, 0, 0, tid, gv);
            stash_half(smem, E_A0, 0, tid, gv);
            gather_half(x4, ea4, u4, sDst, sSrc, sBB, eBase, 0, 4, tid, gv);
            stash_half(smem, E_A0, 4, tid, gv);
        }
        __syncthreads();

        for (int t = 0; t < TPB; t++) {
            const uint32_t aCur = (t & 1) ? E_A1 : E_A0;
            const uint32_t aNxt = (t & 1) ? E_A0 : E_A1;

            float acc[4][4];
            init_acc((const float*)(smem + E_BIAS), nh, lane, acc);

            float4 gv[4];
            if (t + 1 < TPB)
                gather_half(x4, ea4, u4, sDst, sSrc, sBB, eBase, t + 1, 0, tid, gv);

            gemm_half(sb, aCur, E_B, mt, nh, lane, acc, 0);   // hides LDG latency

            if (t + 1 < TPB) {
                stash_half(smem, aNxt, 0, tid, gv);
                gather_half(x4, ea4, u4, sDst, sSrc, sBB, eBase, t + 1, 4, tid, gv);
            }

            gemm_half(sb, aCur, E_B, mt, nh, lane, acc, 4);

            if (t + 1 < TPB)
                stash_half(smem, aNxt, 4, tid, gv);

            {   // relu + v4 scatter (bias already in acc)
                const int da = sDst[t * MTILE + ra];
                const int db = sDst[t * MTILE + rb];
                float* pa = g_agg + (size_t)da * OUTD + (lane & 3) * 4;
                float* pb = g_agg + (size_t)db * OUTD + (lane & 3) * 4;
                #pragma unroll
                for (int p = 0; p < 2; p++) {
                    const int np = nh * 2 + p;
                    red4(pa + np * 16,
                         fmaxf(acc[2*p][0], 0.f),   fmaxf(acc[2*p][1], 0.f),
                         fmaxf(acc[2*p+1][0], 0.f), fmaxf(acc[2*p+1][1], 0.f));
                    red4(pb + np * 16,
                         fmaxf(acc[2*p][2], 0.f),   fmaxf(acc[2*p][3], 0.f),
                         fmaxf(acc[2*p+1][2], 0.f), fmaxf(acc[2*p+1][3], 0.f));
                }
            }
            __syncthreads();   // A-buffer reads done; next stash / index rewrite safe
        }
    }
}

// ==================== node kernel (fp16 1-pass) ====================
__global__ void __launch_bounds__(THREADS, 2) node_kernel(
    const float* __restrict__ x, const float* __restrict__ u,
    const float* __restrict__ b2, float* __restrict__ out)
{
    extern __shared__ char smem[];
    const uint32_t sb = smem_u32(smem);
    const int tid = threadIdx.x;
    const long long n0 = (long long)blockIdx.x * MTILE;

    int* sBB = (int*)(smem + N_BB);
    if (tid < MTILE) {
        long long nn = n0 + tid;
        if (nn >= NNODES) nn = NNODES - 1;
        sBB[tid] = g_batch[nn];
    }
    if (tid < OUTD) ((float*)(smem + N_BIAS))[tid] = b2[tid];
    {   // copy W2 fp16
        const float4* w4 = (const float4*)g_w2f16;
        float4* d4 = (float4*)(smem + N_B);
        #pragma unroll
        for (int i = 0; i < 1024 / THREADS; i++)
            d4[tid + i * THREADS] = w4[tid + i * THREADS];
    }
    __syncthreads();

    {   // batched gather: full 128x32 float4 coverage = 8 iters/thread
        const float4* x4 = (const float4*)x;
        const float4* u4 = (const float4*)u;
        const float4* agg4 = (const float4*)g_agg;
        float4 gv[8];
        int gr[8], gseg[8];
        #pragma unroll
        for (int it = 0; it < 8; it++) {
            int idx = tid + it * THREADS;
            int r = idx >> 5, seg = idx & 31;
            gr[it] = r; gseg[it] = seg;
            long long nn = n0 + r;
            if (nn >= NNODES) nn = NNODES - 1;
            const float4* p;
            if (seg < 8)       p = x4   + (size_t)nn * 8 + seg;
            else if (seg < 24) p = agg4 + (size_t)nn * 16 + (seg - 8);
            else               p = u4   + (size_t)sBB[r] * 8 + (seg - 24);
            gv[it] = *p;
        }
        #pragma unroll
        for (int it = 0; it < 8; it++) {
            uint32_t w0 = (uint32_t)(gseg[it] * 2);
            *(uint32_t*)(smem + N_A + swz(gr[it], w0))     = pack_f16(gv[it].x, gv[it].y);
            *(uint32_t*)(smem + N_A + swz(gr[it], w0 + 1)) = pack_f16(gv[it].z, gv[it].w);
        }
    }
    __syncthreads();

    const int lane = tid & 31, warp = tid >> 5;
    const int mt = warp >> 1, nh = warp & 1;
    float acc[4][4];
    init_acc((const float*)(smem + N_BIAS), nh, lane, acc);

    gemm_half(sb, N_A, N_B, mt, nh, lane, acc, 0);
    gemm_half(sb, N_A, N_B, mt, nh, lane, acc, 4);

    {   // relu + float4 store
        long long ra = n0 + mt * 16 + (lane >> 2);
        long long rb = ra + 8;
        #pragma unroll
        for (int p = 0; p < 2; p++) {
            const int np = nh * 2 + p;
            int c = np * 16 + (lane & 3) * 4;
            if (ra < NNODES)
                *(float4*)(out + (size_t)ra * OUTD + c) = make_float4(
                    fmaxf(acc[2*p][0], 0.f),   fmaxf(acc[2*p][1], 0.f),
                    fmaxf(acc[2*p+1][0], 0.f), fmaxf(acc[2*p+1][1], 0.f));
            if (rb < NNODES)
                *(float4*)(out + (size_t)rb * OUTD + c) = make_float4(
                    fmaxf(acc[2*p][2], 0.f),   fmaxf(acc[2*p][3], 0.f),
                    fmaxf(acc[2*p+1][2], 0.f), fmaxf(acc[2*p+1][3], 0.f));
        }
    }
}

// ==================== launcher ====================
extern "C" void kernel_launch(void* const* d_in, const int* in_sizes, int n_in,
                              void* d_out, int out_size) {
    const float* x     = (const float*)d_in[0];
    const void*  ei    = d_in[1];
    const float* ea    = (const float*)d_in[2];
    const float* u     = (const float*)d_in[3];
    const void*  batch = d_in[4];
    const float* W1    = (const float*)d_in[5];
    const float* b1    = (const float*)d_in[6];
    const float* W2    = (const float*)d_in[7];
    const float* b2    = (const float*)d_in[8];
    float* out = (float*)d_out;

    cudaFuncSetAttribute(edge_kernel, cudaFuncAttributeMaxDynamicSharedMemorySize, E_SZ);
    cudaFuncSetAttribute(node_kernel, cudaFuncAttributeMaxDynamicSharedMemorySize, N_SZ);

    prep_kernel<<<1480, 256>>>(ei, batch, W1, W2);
    edge_kernel<<<EDGE_GRID, THREADS, E_SZ>>>(x, ea, u, b1);
    node_kernel<<<NODE_BLOCKS, THREADS, N_SZ>>>(x, u, b2, out);
}